// round 7
// baseline (speedup 1.0000x reference)
#include <cuda_runtime.h>
#include <cuda_bf16.h>
#include <cstdint>

// Problem dims (fixed by the dataset)
#define Bz 32
#define Tz 1000
#define Hz 512
#define Vz 2048
#define Lz 100
#define BTz (Bz*Tz)
#define Sz (2*Lz+1)           // 201
#define NLAB 101              // blank + L labels
#define NEGINF (-1e10f)
#define CCOMP 5.0f            // per-step decay compensation (probs stored * e^C)
#define LN2F 0.69314718055994531f

// ---------------- device scratch (static: no allocation) ----------------
__device__ __nv_bfloat16 g_Abf[BTz*Hz];        // eouts in bf16 (~32.8 MB)
__device__ __nv_bfloat16 g_Wbf[Vz*Hz];         // W in bf16 (2 MB)
__device__ __nv_bfloat16 g_Wlab[Bz*128*Hz];    // gathered label W rows (padded to 128)
__device__ float         g_blab[Bz*128];       // gathered label biases
__device__ float         g_lse[BTz];           // logsumexp per (b,t)
__device__ float         g_lab[(size_t)BTz*NLAB]; // label probs * e^C
__device__ float         g_lossb[Bz];

// ---------------- helpers ----------------
__device__ __forceinline__ void mma16816(float* c, uint32_t a0, uint32_t a1,
                                         uint32_t a2, uint32_t a3,
                                         uint32_t b0, uint32_t b1) {
    asm volatile(
        "mma.sync.aligned.m16n8k16.row.col.f32.bf16.bf16.f32 "
        "{%0,%1,%2,%3}, {%4,%5,%6,%7}, {%8,%9}, {%0,%1,%2,%3};\n"
        : "+f"(c[0]), "+f"(c[1]), "+f"(c[2]), "+f"(c[3])
        : "r"(a0), "r"(a1), "r"(a2), "r"(a3), "r"(b0), "r"(b1));
}
__device__ __forceinline__ float exp2i(int j) {   // exact 2^j for j in [-126,127]; 0 below
    if (j < -126) return 0.f;
    if (j > 127)  j = 127;
    return __uint_as_float((uint32_t)(127 + j) << 23);
}

#define A_STR 520   // bf16 elems per A smem row (512 + 8 pad -> conflict-free LDS)
#define W_STR 72    // bf16 elems per W smem row (64 + 8 pad)
#define SMEM_BYTES ((128*A_STR + 2*128*W_STR) * 2)

// ---------------- kernel 1: fp32 -> bf16 conversion ----------------
__global__ void k_convert(const float* __restrict__ e, const float* __restrict__ Wm) {
    const int nA2 = (BTz*Hz)/2, nW2 = (Vz*Hz)/2;
    __nv_bfloat162* A2 = reinterpret_cast<__nv_bfloat162*>(g_Abf);
    __nv_bfloat162* W2 = reinterpret_cast<__nv_bfloat162*>(g_Wbf);
    const float2* e2 = reinterpret_cast<const float2*>(e);
    const float2* w2 = reinterpret_cast<const float2*>(Wm);
    for (int i = blockIdx.x*blockDim.x + threadIdx.x; i < nA2 + nW2;
         i += gridDim.x*blockDim.x) {
        if (i < nA2) { float2 v = e2[i]; A2[i] = __floats2bfloat162_rn(v.x, v.y); }
        else         { float2 v = w2[i-nA2]; W2[i-nA2] = __floats2bfloat162_rn(v.x, v.y); }
    }
}

// ---------------- kernel 2: gather label W rows + biases ----------------
__global__ void k_gather(const float* __restrict__ bias, const int* __restrict__ ys) {
    int idx = blockIdx.x;            // b*128 + j
    int b = idx >> 7, j = idx & 127;
    int v = (j == 0) ? 0 : ((j <= Lz) ? ys[b*Lz + j - 1] : -1);
    uint4* dst = reinterpret_cast<uint4*>(g_Wlab + (size_t)idx*Hz);
    if (v >= 0) {
        const uint4* src = reinterpret_cast<const uint4*>(g_Wbf + (size_t)v*Hz);
        dst[threadIdx.x] = src[threadIdx.x];
    } else {
        dst[threadIdx.x] = make_uint4(0u,0u,0u,0u);
    }
    if (threadIdx.x == 0) g_blab[idx] = (v >= 0) ? bias[v] : 0.f;
}

// ---------------- kernel 3: GEMM + online logsumexp (proven round-1/4 code) ----------------
__global__ __launch_bounds__(256, 1) void k_lse(const float* __restrict__ bias) {
    extern __shared__ __nv_bfloat16 sm[];
    __nv_bfloat16* As = sm;                 // [128][A_STR]
    __nv_bfloat16* Ws = sm + 128*A_STR;     // [2][128][W_STR]
    const int tid = threadIdx.x;
    const int w = tid >> 5, lane = tid & 31, g = lane >> 2, tig = lane & 3;
    const int r0 = blockIdx.x * 128;
    const int rowA = w*16 + g;

    for (int e = tid; e < 128*64; e += 256) {
        int row = e >> 6, c = e & 63;
        *reinterpret_cast<uint4*>(As + row*A_STR + c*8) =
            *reinterpret_cast<const uint4*>(g_Abf + (size_t)(r0+row)*Hz + c*8);
    }

    float M0 = -3e38f, S0 = 0.f, M1 = -3e38f, S1 = 0.f;

    #pragma unroll 1
    for (int nc = 0; nc < Vz/128; nc++) {
        const int vbase = nc * 128;
        uint2 rg[8];
        #pragma unroll
        for (int q = 0; q < 8; q++) {
            int e = tid + q*256; int row = e >> 4, c = e & 15;
            rg[q] = *reinterpret_cast<const uint2*>(g_Wbf + (size_t)(vbase+row)*Hz + c*4);
        }
        #pragma unroll
        for (int q = 0; q < 8; q++) {
            int e = tid + q*256; int row = e >> 4, c = e & 15;
            *reinterpret_cast<uint2*>(Ws + row*W_STR + c*4) = rg[q];
        }
        __syncthreads();

        float acc[16][4];
        #pragma unroll
        for (int i = 0; i < 16; i++) { acc[i][0]=0.f; acc[i][1]=0.f; acc[i][2]=0.f; acc[i][3]=0.f; }

        #pragma unroll 1
        for (int kc = 0; kc < 8; kc++) {
            if (kc < 7) {
                #pragma unroll
                for (int q = 0; q < 8; q++) {
                    int e = tid + q*256; int row = e >> 4, c = e & 15;
                    rg[q] = *reinterpret_cast<const uint2*>(
                        g_Wbf + (size_t)(vbase+row)*Hz + (kc+1)*64 + c*4);
                }
            }
            const __nv_bfloat16* Wb = Ws + (kc & 1) * (128*W_STR);
            #pragma unroll
            for (int ks = 0; ks < 4; ks++) {
                const int kk = kc*64 + ks*16;
                uint32_t a0 = *reinterpret_cast<const uint32_t*>(As + rowA*A_STR + kk + 2*tig);
                uint32_t a1 = *reinterpret_cast<const uint32_t*>(As + (rowA+8)*A_STR + kk + 2*tig);
                uint32_t a2 = *reinterpret_cast<const uint32_t*>(As + rowA*A_STR + kk + 8 + 2*tig);
                uint32_t a3 = *reinterpret_cast<const uint32_t*>(As + (rowA+8)*A_STR + kk + 8 + 2*tig);
                #pragma unroll
                for (int nt = 0; nt < 16; nt++) {
                    uint32_t b0 = *reinterpret_cast<const uint32_t*>(Wb + (nt*8+g)*W_STR + ks*16 + 2*tig);
                    uint32_t b1 = *reinterpret_cast<const uint32_t*>(Wb + (nt*8+g)*W_STR + ks*16 + 8 + 2*tig);
                    mma16816(acc[nt], a0, a1, a2, a3, b0, b1);
                }
            }
            __syncthreads();
            if (kc < 7) {
                __nv_bfloat16* Wd = Ws + ((kc+1) & 1) * (128*W_STR);
                #pragma unroll
                for (int q = 0; q < 8; q++) {
                    int e = tid + q*256; int row = e >> 4, c = e & 15;
                    *reinterpret_cast<uint2*>(Wd + row*W_STR + c*4) = rg[q];
                }
                __syncthreads();
            }
        }

        float m0 = -3e38f, m1 = -3e38f;
        #pragma unroll
        for (int nt = 0; nt < 16; nt++) {
            int v = vbase + nt*8 + 2*tig;
            float bb0 = __ldg(&bias[v]), bb1 = __ldg(&bias[v+1]);
            acc[nt][0] += bb0; acc[nt][1] += bb1; acc[nt][2] += bb0; acc[nt][3] += bb1;
            m0 = fmaxf(m0, fmaxf(acc[nt][0], acc[nt][1]));
            m1 = fmaxf(m1, fmaxf(acc[nt][2], acc[nt][3]));
        }
        float s0 = 0.f, s1 = 0.f;
        #pragma unroll
        for (int nt = 0; nt < 16; nt++) {
            s0 += __expf(acc[nt][0]-m0) + __expf(acc[nt][1]-m0);
            s1 += __expf(acc[nt][2]-m1) + __expf(acc[nt][3]-m1);
        }
        #pragma unroll
        for (int off = 1; off <= 2; off <<= 1) {
            float mo = __shfl_xor_sync(0xffffffffu, m0, off);
            float so = __shfl_xor_sync(0xffffffffu, s0, off);
            float mn = fmaxf(m0, mo);
            s0 = s0*__expf(m0-mn) + so*__expf(mo-mn); m0 = mn;
            mo = __shfl_xor_sync(0xffffffffu, m1, off);
            so = __shfl_xor_sync(0xffffffffu, s1, off);
            mn = fmaxf(m1, mo);
            s1 = s1*__expf(m1-mn) + so*__expf(mo-mn); m1 = mn;
        }
        { float mn = fmaxf(M0, m0); S0 = S0*__expf(M0-mn) + s0*__expf(m0-mn); M0 = mn; }
        { float mn = fmaxf(M1, m1); S1 = S1*__expf(M1-mn) + s1*__expf(m1-mn); M1 = mn; }
    }

    if (tig == 0) {
        g_lse[r0 + rowA]     = M0 + __logf(S0);
        g_lse[r0 + rowA + 8] = M1 + __logf(S1);
    }
}

// ---------------- kernel 4: label-logit GEMM -> probs (exp, +CCOMP) ----------------
__global__ __launch_bounds__(256, 1) void k_lab() {
    extern __shared__ __nv_bfloat16 sm[];
    __nv_bfloat16* As = sm;
    __nv_bfloat16* Ws = sm + 128*A_STR;
    const int tid = threadIdx.x;
    const int w = tid >> 5, lane = tid & 31, g = lane >> 2, tig = lane & 3;
    const int mc = blockIdx.x, b = blockIdx.y;
    const int t0 = mc * 128;
    const __nv_bfloat16* Wsrc = g_Wlab + (size_t)b*128*Hz;

    for (int e = tid; e < 128*64; e += 256) {
        int row = e >> 6, c = e & 63;
        int t = t0 + row; if (t > Tz-1) t = Tz-1;
        *reinterpret_cast<uint4*>(As + row*A_STR + c*8) =
            *reinterpret_cast<const uint4*>(g_Abf + (size_t)(b*Tz + t)*Hz + c*8);
    }

    uint2 rg[8];
    #pragma unroll
    for (int q = 0; q < 8; q++) {
        int e = tid + q*256; int row = e >> 4, c = e & 15;
        rg[q] = *reinterpret_cast<const uint2*>(Wsrc + (size_t)row*Hz + c*4);
    }
    #pragma unroll
    for (int q = 0; q < 8; q++) {
        int e = tid + q*256; int row = e >> 4, c = e & 15;
        *reinterpret_cast<uint2*>(Ws + row*W_STR + c*4) = rg[q];
    }
    __syncthreads();

    float acc[16][4];
    #pragma unroll
    for (int i = 0; i < 16; i++) { acc[i][0]=0.f; acc[i][1]=0.f; acc[i][2]=0.f; acc[i][3]=0.f; }

    #pragma unroll 1
    for (int kc = 0; kc < 8; kc++) {
        if (kc < 7) {
            #pragma unroll
            for (int q = 0; q < 8; q++) {
                int e = tid + q*256; int row = e >> 4, c = e & 15;
                rg[q] = *reinterpret_cast<const uint2*>(Wsrc + (size_t)row*Hz + (kc+1)*64 + c*4);
            }
        }
        const __nv_bfloat16* Wb = Ws + (kc & 1) * (128*W_STR);
        const int rowA = w*16 + g;
        #pragma unroll
        for (int ks = 0; ks < 4; ks++) {
            const int kk = kc*64 + ks*16;
            uint32_t a0 = *reinterpret_cast<const uint32_t*>(As + rowA*A_STR + kk + 2*tig);
            uint32_t a1 = *reinterpret_cast<const uint32_t*>(As + (rowA+8)*A_STR + kk + 2*tig);
            uint32_t a2 = *reinterpret_cast<const uint32_t*>(As + rowA*A_STR + kk + 8 + 2*tig);
            uint32_t a3 = *reinterpret_cast<const uint32_t*>(As + (rowA+8)*A_STR + kk + 8 + 2*tig);
            #pragma unroll
            for (int nt = 0; nt < 16; nt++) {
                uint32_t b0 = *reinterpret_cast<const uint32_t*>(Wb + (nt*8+g)*W_STR + ks*16 + 2*tig);
                uint32_t b1 = *reinterpret_cast<const uint32_t*>(Wb + (nt*8+g)*W_STR + ks*16 + 8 + 2*tig);
                mma16816(acc[nt], a0, a1, a2, a3, b0, b1);
            }
        }
        __syncthreads();
        if (kc < 7) {
            __nv_bfloat16* Wd = Ws + ((kc+1) & 1) * (128*W_STR);
            #pragma unroll
            for (int q = 0; q < 8; q++) {
                int e = tid + q*256; int row = e >> 4, c = e & 15;
                *reinterpret_cast<uint2*>(Wd + row*W_STR + c*4) = rg[q];
            }
            __syncthreads();
        }
    }

    const int rowA = w*16 + g;
    int ta = t0 + rowA, tb = ta + 8;
    float lseA = (ta < Tz) ? g_lse[b*Tz + ta] : 0.f;
    float lseB = (tb < Tz) ? g_lse[b*Tz + tb] : 0.f;
    #pragma unroll
    for (int nt = 0; nt < 16; nt++) {
        int c0 = nt*8 + 2*tig, c1 = c0 + 1;
        float bb0 = g_blab[b*128 + c0], bb1 = g_blab[b*128 + c1];
        if (ta < Tz) {
            if (c0 < NLAB) g_lab[(size_t)(b*Tz+ta)*NLAB + c0] = __expf(acc[nt][0] + bb0 - lseA + CCOMP);
            if (c1 < NLAB) g_lab[(size_t)(b*Tz+ta)*NLAB + c1] = __expf(acc[nt][1] + bb1 - lseA + CCOMP);
        }
        if (tb < Tz) {
            if (c0 < NLAB) g_lab[(size_t)(b*Tz+tb)*NLAB + c0] = __expf(acc[nt][2] + bb0 - lseB + CCOMP);
            if (c1 < NLAB) g_lab[(size_t)(b*Tz+tb)*NLAB + c1] = __expf(acc[nt][3] + bb1 - lseB + CCOMP);
        }
    }
}

// ---------------- kernel 5: CTC forward DP (linear domain, PER-WARP exponents) ----------------
// 7 warps x 64 states (32 own + 32 left halo), interleaved (even,odd) per lane.
// Step = shfl + adds + mults (no MUFU). Every 8 steps: warp max -> rescale so the
// warp max sits at 2^30 (108-nat downside window per warp); halo imported from the
// neighbor with exact power-of-two exponent reconciliation.
__global__ __launch_bounds__(224) void k_dp(const int* __restrict__ ys,
                                            const int* __restrict__ elens,
                                            const int* __restrict__ ylens) {
    __shared__ float sA[224];
    __shared__ int   sE[8];   // per-warp absolute exponent (old, as of publish)
    __shared__ int   sM[8];   // per-warp max magnitude exponent; SENT if warp all-zero
    const int SENT = -(1 << 29);
    const int b = blockIdx.x;
    const int tid = threadIdx.x, w = tid >> 5, lane = tid & 31;
    const int elen = elens[b], ylen = ylens[b];
    const int smax = 2*ylen + 1;
    const int s0 = 32*w - 32 + 2*lane;
    const int s1 = s0 + 1;
    const bool v0 = (s0 >= 0) && (s0 < smax);
    const bool v1 = (s1 >= 0) && (s1 < smax);
    const int yidx = (s1 >= 1) ? (s1 >> 1) : 0;
    const int j1c  = min(max(yidx + 1, 0), NLAB - 1);
    bool skip1 = false;
    if (s1 >= 3 && yidx >= 1 && yidx <= Lz - 1)
        skip1 = (ys[b*Lz + yidx] != ys[b*Lz + yidx - 1]);
    const float* lab = g_lab + (size_t)b*Tz*NLAB;

    float r0 = (v0 && s0 == 0) ? __ldg(lab + 0) : 0.f;
    float r1 = (v1 && s1 == 1) ? __ldg(lab + 1) : 0.f;

    // 4-deep prob prefetch (t = 1..4); pB* broadcast, p1* coalesced
    float pB0 = __ldg(lab + 1*NLAB), p10 = __ldg(lab + 1*NLAB + j1c);
    float pB1 = __ldg(lab + 2*NLAB), p11 = __ldg(lab + 2*NLAB + j1c);
    float pB2 = __ldg(lab + 3*NLAB), p12 = __ldg(lab + 3*NLAB + j1c);
    float pB3 = __ldg(lab + 4*NLAB), p13 = __ldg(lab + 4*NLAB + j1c);

    int Ew = 0;   // this warp's absolute base-2 exponent

    auto step = [&](int t) {
        float r1m = __shfl_up_sync(0xffffffffu, r1, 1);
        if (lane == 0) r1m = 0.f;
        float n0 = (r0 + r1m) * pB0;                       // blank: s0, s0-1
        float x2 = skip1 ? r1m : 0.f;
        float n1 = (r1 + r0 + x2) * p10;                   // label: s1, s1-1, s1-2
        r0 = v0 ? n0 : 0.f;
        r1 = v1 ? n1 : 0.f;
        pB0 = pB1; p10 = p11; pB1 = pB2; p11 = p12; pB2 = pB3; p12 = p13;
        int tn = t + 4; if (tn > elen - 1) tn = elen - 1;
        const float* q = lab + (size_t)tn * NLAB;
        pB3 = __ldg(q); p13 = __ldg(q + j1c);
    };

    int t = 1;
    while (t < elen) {
        int rem = elen - t;
        if (rem >= 8) {
            #pragma unroll
            for (int k = 0; k < 8; k++) step(t + k);
            t += 8;
        } else {
            #pragma unroll 1
            for (int k = 0; k < rem; k++) step(t + k);
            t += rem;
        }
        // publish state + per-warp max exponent
        float lm = fmaxf(r0, r1);
        #pragma unroll
        for (int off = 16; off >= 1; off >>= 1)
            lm = fmaxf(lm, __shfl_xor_sync(0xffffffffu, lm, off));
        if (lane >= 16) { sA[s0] = r0; sA[s1] = r1; }
        if (lane == 0) {
            sE[w] = Ew;
            sM[w] = (lm > 0.f)
                ? (Ew + (int)((__float_as_uint(lm) >> 23) & 0xFFu) - 127)
                : SENT;
        }
        __syncthreads();
        const int eown = sM[w];
        const int enbr = (w > 0) ? sM[w-1] : SENT;
        const int Enbr_old = (w > 0) ? sE[w-1] : 0;
        const int etop = (eown > enbr) ? eown : enbr;
        if (etop > SENT) {
            const int Enew = etop - 30;                    // warp max -> 2^30
            int kk = Ew - Enew;
            float h0 = r0, h1 = r1;
            if (lane < 16 && w > 0) {                      // halo import at nbr scale
                h0 = sA[s0]; h1 = sA[s1]; kk = Enbr_old - Enew;
            }
            const int k1 = kk >> 1, k2 = kk - (kk >> 1);   // exact two-factor 2^kk
            const float f1 = exp2i(k1), f2 = exp2i(k2);
            r0 = h0 * f1 * f2;
            r1 = h1 * f1 * f2;
            Ew = Enew;
        } else {
            if (lane < 16 && w > 0) { r0 = sA[s0]; r1 = sA[s1]; }   // zeros
        }
        __syncthreads();
    }

    // final publish with per-warp exponents
    if (lane >= 16) { sA[s0] = r0; sA[s1] = r1; }
    if (lane == 0) sE[w] = Ew;
    __syncthreads();
    if (tid == 0) {
        const int ya = 2*ylen;
        float a = sA[ya],    c = sA[ya - 1];
        int  Ea = sE[ya >> 5], Ec = sE[(ya - 1) >> 5];
        float La = (a > 0.f) ? (__logf(a) + (float)Ea * LN2F) : -3e38f;
        float Lc = (c > 0.f) ? (__logf(c) + (float)Ec * LN2F) : -3e38f;
        float m = fmaxf(La, Lc);
        float loss;
        if (m < -1e37f) loss = 1e30f;   // both zero -> +inf analogue
        else loss = CCOMP * (float)elen - (m + __logf(__expf(La - m) + __expf(Lc - m)));
        g_lossb[b] = (loss < -0.5f*NEGINF) ? loss : 0.f;
    }
}

// ---------------- kernel 6: deterministic finalize ----------------
__global__ void k_final(float* __restrict__ out) {
    if (threadIdx.x == 0 && blockIdx.x == 0) {
        float s = 0.f;
        for (int b = 0; b < Bz; b++) s += g_lossb[b];
        out[0] = s / (float)Bz;
    }
}

// ---------------- entry ----------------
extern "C" void kernel_launch(void* const* d_in, const int* in_sizes, int n_in,
                              void* d_out, int out_size) {
    const float* eouts = (const float*)d_in[0];
    const float* W     = (const float*)d_in[1];
    const float* bias  = (const float*)d_in[2];
    const int*   ys    = (const int*)d_in[3];
    const int*   elens = (const int*)d_in[4];
    const int*   ylens = (const int*)d_in[5];
    float* out = (float*)d_out;

    cudaFuncSetAttribute(k_lse, cudaFuncAttributeMaxDynamicSharedMemorySize, SMEM_BYTES);
    cudaFuncSetAttribute(k_lab, cudaFuncAttributeMaxDynamicSharedMemorySize, SMEM_BYTES);

    k_convert<<<2048, 256>>>(eouts, W);
    k_gather<<<Bz*128, 64>>>(bias, ys);
    k_lse<<<BTz/128, 256, SMEM_BYTES>>>(bias);
    k_lab<<<dim3((Tz + 127)/128, Bz), 256, SMEM_BYTES>>>();
    k_dp<<<Bz, 224>>>(ys, elens, ylens);
    k_final<<<1, 32>>>(out);
}